// round 14
// baseline (speedup 1.0000x reference)
#include <cuda_runtime.h>
#include <cuda_fp16.h>
#include <cstdint>

#define N_NODES 100000
#define M_HE    200000
#define NE      2000000
#define IN_F    16
#define HID     64
#define NT      2

#define SB (NT * M_HE)     // 400000
#define SD (NT * N_NODES)  // 200000
#define NBB ((SB + 1023) / 1024)   // 391
#define NBD ((SD + 1023) / 1024)   // 196
#define TILES ((N_NODES + 63) / 64)  // 1563
#define XW_TILES (N_NODES / 16)      // 6250
#define XW_PERS 152
#define HIST_BLOCKS ((NE + 255) / 256)

// ---------------- scratch ----------------
__device__ __align__(16) __half g_xw_h[(size_t)N_NODES * 128];
__device__ __align__(16) __half g_efeat_h[(size_t)M_HE * 128];
__device__ __align__(16) __half g_u_h[(size_t)N_NODES * 128];
__device__ __align__(16) __half g_h_h[(size_t)N_NODES * HID];
__device__ int g_hB[SB], g_hD[SD];
__device__ int g_offB[SB + 1], g_offD[SD + 1];
__device__ int g_curB[SB], g_curD[SD];
__device__ unsigned long long g_flagB[NBB], g_flagD[NBD];
__device__ int g_idxB[NE];
__device__ int g_idxD[NE];

// ---------------- launch 0: persistent xw projection + histogram + flag zero ----------------
__global__ void k_xw_hist(const float* __restrict__ x, const float* __restrict__ Wc,
                          const int* __restrict__ en, const int* __restrict__ eh,
                          const int* __restrict__ ea) {
    if (blockIdx.x < XW_PERS) {
        __shared__ float Ws[NT * IN_F * HID];
        __shared__ float xs[16 * IN_F];
        int tid = threadIdx.x;
        for (int i = tid; i < NT * IN_F * HID; i += 256) Ws[i] = Wc[i];
        int c = tid & 127;
        int hf = tid >> 7;
        int t = c >> 6, cc = c & 63;
        const float* w = &Ws[t * (IN_F * HID) + cc];
        for (int tile = blockIdx.x; tile < XW_TILES; tile += XW_PERS) {
            int n0 = tile * 16;
            __syncthreads();   // protect xs from previous iteration's readers
            xs[tid] = x[(size_t)n0 * IN_F + tid];
            __syncthreads();
            #pragma unroll
            for (int nd = 0; nd < 8; nd++) {
                int node = n0 + hf * 8 + nd;
                float a = 0.f;
                #pragma unroll
                for (int k = 0; k < IN_F; k++) a += xs[(hf * 8 + nd) * IN_F + k] * w[k * HID];
                float a_hi = __shfl_down_sync(0xffffffffu, a, 1);
                if ((c & 1) == 0) {
                    __half2 hv = __floats2half2_rn(a, a_hi);
                    ((__half2*)g_xw_h)[((size_t)node * 128 + c) >> 1] = hv;
                }
            }
        }
    } else {
        int hb = blockIdx.x - XW_PERS;
        if (hb == 0) {
            for (int f = threadIdx.x; f < NBB; f += 256) g_flagB[f] = 0ull;
            for (int f = threadIdx.x; f < NBD; f += 256) g_flagD[f] = 0ull;
        }
        int i = hb * 256 + threadIdx.x;
        if (i >= NE) return;
        int t = ea[i];
        atomicAdd(&g_hB[t * M_HE + eh[i]], 1);
        atomicAdd(&g_hD[t * N_NODES + en[i]], 1);
    }
}

// ---------------- launch 1: single-pass scan (decoupled lookback) ----------------
__global__ void k_scan() {
    int b = blockIdx.x;
    bool isD = (b >= NBB);
    int cb = isD ? b - NBB : b;
    const int n = isD ? SD : SB;
    const int nb = isD ? NBD : NBB;
    int* hist = isD ? g_hD : g_hB;
    int* out  = isD ? g_offD : g_offB;
    int* cur  = isD ? g_curD : g_curB;
    volatile unsigned long long* flags = isD ? g_flagD : g_flagB;

    int tid = threadIdx.x;
    int base = cb * 1024 + tid * 4;
    int v0 = (base + 0 < n) ? hist[base + 0] : 0;
    int v1 = (base + 1 < n) ? hist[base + 1] : 0;
    int v2 = (base + 2 < n) ? hist[base + 2] : 0;
    int v3 = (base + 3 < n) ? hist[base + 3] : 0;
    if (base + 0 < n) hist[base + 0] = 0;
    if (base + 1 < n) hist[base + 1] = 0;
    if (base + 2 < n) hist[base + 2] = 0;
    if (base + 3 < n) hist[base + 3] = 0;
    int s = v0 + v1 + v2 + v3;
    __shared__ int sh[256];
    __shared__ int s_prev;
    sh[tid] = s;
    __syncthreads();
    for (int d = 1; d < 256; d <<= 1) {
        int v = (tid >= d) ? sh[tid - d] : 0;
        __syncthreads();
        sh[tid] += v;
        __syncthreads();
    }
    int excl = sh[tid] - s;

    if (tid == 255) {
        int total = excl + s;
        int prev = 0;
        if (cb == 0) {
            flags[0] = (2ull << 62) | (unsigned long long)(unsigned)total;
        } else {
            flags[cb] = (1ull << 62) | (unsigned long long)(unsigned)total;
            for (int p = cb - 1; p >= 0; p--) {
                unsigned long long f;
                do { f = flags[p]; } while ((f >> 62) == 0ull);
                prev += (int)(unsigned)(f & 0xffffffffull);
                if ((f >> 62) == 2ull) break;
            }
            flags[cb] = (2ull << 62) | (unsigned long long)(unsigned)(prev + total);
        }
        s_prev = prev;
    }
    __syncthreads();
    int p0 = s_prev + excl;
    if (base + 0 < n) { out[base + 0] = p0;                cur[base + 0] = p0; }
    if (base + 1 < n) { out[base + 1] = p0 + v0;           cur[base + 1] = p0 + v0; }
    if (base + 2 < n) { out[base + 2] = p0 + v0 + v1;      cur[base + 2] = p0 + v0 + v1; }
    if (base + 3 < n) { out[base + 3] = p0 + v0 + v1 + v2; cur[base + 3] = p0 + v0 + v1 + v2; }
    if (tid == 0 && cb == nb - 1) out[n] = NE;
}

// ---------------- launch 2: placement ----------------
__global__ void k_place(const int* __restrict__ en, const int* __restrict__ eh,
                        const int* __restrict__ ea) {
    int i = blockIdx.x * blockDim.x + threadIdx.x;
    if (i >= NE) return;
    int t = ea[i], n = en[i], he = eh[i];
    int pb = atomicAdd(&g_curB[t * M_HE + he], 1);
    g_idxB[pb] = n;
    int pd = atomicAdd(&g_curD[t * N_NODES + n], 1);
    g_idxD[pd] = he;
}

__device__ __forceinline__ void accum8(float* s, uint4 v) {
    const __half2* h = (const __half2*)&v;
    #pragma unroll
    for (int i = 0; i < 4; i++) {
        float2 f = __half22float2(h[i]);
        s[2 * i]     += f.x;
        s[2 * i + 1] += f.y;
    }
}

__device__ __forceinline__ void accum4x(float* s, uint4 v0, uint4 v1, uint4 v2, uint4 v3) {
    const __half2* h0 = (const __half2*)&v0;
    const __half2* h1 = (const __half2*)&v1;
    const __half2* h2 = (const __half2*)&v2;
    const __half2* h3 = (const __half2*)&v3;
    #pragma unroll
    for (int i = 0; i < 4; i++) {
        __half2 ss = __hadd2(__hadd2(h0[i], h1[i]), __hadd2(h2[i], h3[i]));
        float2 f = __half22float2(ss);
        s[2 * i]     += f.x;
        s[2 * i + 1] += f.y;
    }
}

// ---------------- launch 3 (ncu): gather 1 ----------------
__global__ void k_gather1() {
    int idx = blockIdx.x * blockDim.x + threadIdx.x;
    int r = idx >> 3, q = idx & 7;
    if (r >= SB) return;
    int t = (r >= M_HE) ? 1 : 0;
    int he = r - t * M_HE;
    int start = g_offB[r];
    int cnt = g_offB[r + 1] - start;
    const char* xwb = (const char*)g_xw_h + (unsigned)(t * 8 + q) * 16u;
    const int* ip = g_idxB + start;
    float s[8] = {0.f, 0.f, 0.f, 0.f, 0.f, 0.f, 0.f, 0.f};
    int j = 0;
    for (; j + 4 <= cnt; j += 4) {
        unsigned o0 = (unsigned)__ldg(ip + j)     * 256u;
        unsigned o1 = (unsigned)__ldg(ip + j + 1) * 256u;
        unsigned o2 = (unsigned)__ldg(ip + j + 2) * 256u;
        unsigned o3 = (unsigned)__ldg(ip + j + 3) * 256u;
        uint4 v0 = *(const uint4*)(xwb + o0);
        uint4 v1 = *(const uint4*)(xwb + o1);
        uint4 v2 = *(const uint4*)(xwb + o2);
        uint4 v3 = *(const uint4*)(xwb + o3);
        accum4x(s, v0, v1, v2, v3);
    }
    for (; j < cnt; j++) {
        unsigned o = (unsigned)__ldg(ip + j) * 256u;
        accum8(s, *(const uint4*)(xwb + o));
    }
    float binv = (cnt > 0) ? (1.f / (float)cnt) : 0.f;
    uint4 outv;
    __half2* oh = (__half2*)&outv;
    #pragma unroll
    for (int i = 0; i < 4; i++)
        oh[i] = __floats2half2_rn(s[2 * i] * binv, s[2 * i + 1] * binv);
    ((uint4*)g_efeat_h)[(size_t)he * 16 + t * 8 + q] = outv;
}

// ---------------- launch 4: gather 2 (fuses *dinv + b_conv, fp16 out) ----------------
__global__ void k_gather2(const float* __restrict__ bconv) {
    int idx = blockIdx.x * blockDim.x + threadIdx.x;
    int r = idx >> 3, q = idx & 7;
    if (r >= SD) return;
    int t = (r >= N_NODES) ? 1 : 0;
    int n = r - t * N_NODES;
    int start = g_offD[r];
    int cnt = g_offD[r + 1] - start;
    const char* efb = (const char*)g_efeat_h + (unsigned)(t * 8 + q) * 16u;
    const int* ip = g_idxD + start;
    float s[8] = {0.f, 0.f, 0.f, 0.f, 0.f, 0.f, 0.f, 0.f};
    int j = 0;
    for (; j + 4 <= cnt; j += 4) {
        unsigned o0 = (unsigned)__ldg(ip + j)     * 256u;
        unsigned o1 = (unsigned)__ldg(ip + j + 1) * 256u;
        unsigned o2 = (unsigned)__ldg(ip + j + 2) * 256u;
        unsigned o3 = (unsigned)__ldg(ip + j + 3) * 256u;
        uint4 v0 = *(const uint4*)(efb + o0);
        uint4 v1 = *(const uint4*)(efb + o1);
        uint4 v2 = *(const uint4*)(efb + o2);
        uint4 v3 = *(const uint4*)(efb + o3);
        accum4x(s, v0, v1, v2, v3);
    }
    for (; j < cnt; j++) {
        unsigned o = (unsigned)__ldg(ip + j) * 256u;
        accum8(s, *(const uint4*)(efb + o));
    }
    float dinv = (cnt > 0) ? (1.f / (float)cnt) : 0.f;
    int cbase = t * 64 + q * 8;
    float4 b0 = *(const float4*)(bconv + cbase);
    float4 b1 = *(const float4*)(bconv + cbase + 4);
    uint4 outv;
    __half2* oh = (__half2*)&outv;
    oh[0] = __floats2half2_rn(s[0] * dinv + b0.x, s[1] * dinv + b0.y);
    oh[1] = __floats2half2_rn(s[2] * dinv + b0.z, s[3] * dinv + b0.w);
    oh[2] = __floats2half2_rn(s[4] * dinv + b1.x, s[5] * dinv + b1.y);
    oh[3] = __floats2half2_rn(s[6] * dinv + b1.z, s[7] * dinv + b1.w);
    ((uint4*)g_u_h)[(size_t)n * 16 + t * 8 + q] = outv;
}

__device__ __forceinline__ float sigf(float x) { return 1.f / (1.f + expf(-x)); }

#define MMA16816(c0, c1, c2, c3, a0, a1, a2, a3, b0, b1) \
    asm volatile("mma.sync.aligned.m16n8k16.row.col.f32.f16.f16.f32 " \
                 "{%0,%1,%2,%3}, {%4,%5,%6,%7}, {%8,%9}, {%0,%1,%2,%3};" \
                 : "+f"(c0), "+f"(c1), "+f"(c2), "+f"(c3) \
                 : "r"(a0), "r"(a1), "r"(a2), "r"(a3), "r"(b0), "r"(b1))

// ---------------- launch 5: mix via MMA (persistent) ----------------
__global__ __launch_bounds__(256, 1)
void k_mix_mma(const float* __restrict__ Wmix, const float* __restrict__ bmix) {
    extern __shared__ __half sbuf[];
    __half* buf = sbuf;
    int tid = threadIdx.x;
    int lane = tid & 31;
    int wrp = tid >> 5;
    int g = lane >> 2;
    int t = lane & 3;

    for (int i = tid; i < 64 * 128; i += 256) {
        int n = i >> 7, k = i & 127;
        buf[n * 136 + k] = __float2half(Wmix[k * 64 + n]);
    }
    __syncthreads();

    uint32_t Bm[8][2];
    {
        int n = wrp * 8 + g;
        #pragma unroll
        for (int ks = 0; ks < 8; ks++) {
            Bm[ks][0] = *(const uint32_t*)&buf[n * 136 + ks * 16 + 2 * t];
            Bm[ks][1] = *(const uint32_t*)&buf[n * 136 + ks * 16 + 2 * t + 8];
        }
    }
    int col = wrp * 8 + 2 * t;
    float bm0 = bmix[col], bm1 = bmix[col + 1];
    __syncthreads();

    for (int tile = blockIdx.x; tile < TILES; tile += gridDim.x) {
        int n0 = tile * 64;
        for (int i = tid; i < 1024; i += 256) {
            int nd = i >> 4, c8 = (i & 15) * 8;
            int n = n0 + nd;
            uint4 v = make_uint4(0u, 0u, 0u, 0u);
            if (n < N_NODES) v = ((const uint4*)g_u_h)[(size_t)n * 16 + (c8 >> 3)];
            *(uint4*)&buf[nd * 136 + c8] = v;
        }
        __syncthreads();

        float am[4][4];
        #pragma unroll
        for (int m = 0; m < 4; m++)
            #pragma unroll
            for (int c = 0; c < 4; c++) am[m][c] = 0.f;

        #pragma unroll
        for (int ks = 0; ks < 8; ks++) {
            #pragma unroll
            for (int m = 0; m < 4; m++) {
                int row = m * 16 + g;
                int ko = ks * 16 + 2 * t;
                uint32_t a0 = *(const uint32_t*)&buf[row * 136 + ko];
                uint32_t a1 = *(const uint32_t*)&buf[(row + 8) * 136 + ko];
                uint32_t a2 = *(const uint32_t*)&buf[row * 136 + ko + 8];
                uint32_t a3 = *(const uint32_t*)&buf[(row + 8) * 136 + ko + 8];
                MMA16816(am[m][0], am[m][1], am[m][2], am[m][3],
                         a0, a1, a2, a3, Bm[ks][0], Bm[ks][1]);
            }
        }

        #pragma unroll
        for (int m = 0; m < 4; m++) {
            int row = m * 16 + g;
            int na = n0 + row, nb = n0 + row + 8;
            if (na < N_NODES) {
                __half2 hv = __floats2half2_rn(fmaxf(am[m][0] + bm0, 0.f),
                                               fmaxf(am[m][1] + bm1, 0.f));
                *(__half2*)&g_h_h[(size_t)na * 64 + col] = hv;
            }
            if (nb < N_NODES) {
                __half2 hv = __floats2half2_rn(fmaxf(am[m][2] + bm0, 0.f),
                                               fmaxf(am[m][3] + bm1, 0.f));
                *(__half2*)&g_h_h[(size_t)nb * 64 + col] = hv;
            }
        }
        __syncthreads();
    }
}

// ---------------- launch 6: GRU via fp16 mma.sync (persistent) ----------------
__global__ __launch_bounds__(256, 1)
void k_gru_mma(const float* __restrict__ hprev,
               const float* __restrict__ Wih, const float* __restrict__ Whh,
               const float* __restrict__ bih, const float* __restrict__ bhh,
               const float* __restrict__ Wout, const float* __restrict__ bout,
               float* __restrict__ out_h, float* __restrict__ out_p) {
    extern __shared__ float smf[];
    float*  stage = smf;                          // [2][64][196]
    __half* Wih16 = (__half*)smf;                 // [192][72]
    __half* Whh16 = Wih16 + 192 * 72;             // [192][72]
    __half* h16   = (__half*)(smf + 25088);       // [64][72]
    __half* hp16  = h16 + 64 * 72;                // [64][72]
    float*  hnS   = smf + 29696;                  // [64][68]
    float*  bihS  = smf + 34048;
    float*  bhhS  = bihS + 192;
    float*  woS   = bhhS + 192;
    float*  boS   = woS + 192;

    int tid = threadIdx.x;
    int lane = tid & 31;
    int wrp = tid >> 5;
    int g = lane >> 2;
    int t = lane & 3;
    int cbase = wrp * 24;

    if (tid < 192) {
        bihS[tid] = bih[tid];
        bhhS[tid] = bhh[tid];
        int j = tid / 3, k = tid % 3;
        woS[tid] = Wout[j * 64 + k];
    }
    if (tid < 3) boS[tid] = bout[tid];

    for (int i = tid; i < 192 * 64; i += 256) {
        int r = i >> 6, k = i & 63;
        Wih16[r * 72 + k] = __float2half(Wih[i]);
        Whh16[r * 72 + k] = __float2half(Whh[i]);
    }
    __syncthreads();

    uint32_t Bi[3][4][2], Bh[3][4][2];
    #pragma unroll
    for (int nt = 0; nt < 3; nt++) {
        int n = cbase + nt * 8 + g;
        #pragma unroll
        for (int ks = 0; ks < 4; ks++) {
            Bi[nt][ks][0] = *(const uint32_t*)&Wih16[n * 72 + ks * 16 + 2 * t];
            Bi[nt][ks][1] = *(const uint32_t*)&Wih16[n * 72 + ks * 16 + 2 * t + 8];
            Bh[nt][ks][0] = *(const uint32_t*)&Whh16[n * 72 + ks * 16 + 2 * t];
            Bh[nt][ks][1] = *(const uint32_t*)&Whh16[n * 72 + ks * 16 + 2 * t + 8];
        }
    }
    __syncthreads();

    for (int tile = blockIdx.x; tile < TILES; tile += gridDim.x) {
        int n0 = tile * 64;
        for (int i = tid; i < 512; i += 256) {
            int nd = i >> 3, c8 = (i & 7) * 8;
            int n = n0 + nd;
            uint4 v = make_uint4(0u, 0u, 0u, 0u);
            if (n < N_NODES) v = ((const uint4*)g_h_h)[(size_t)n * 8 + (c8 >> 3)];
            *(uint4*)&h16[nd * 72 + c8] = v;
        }
        for (int i = tid; i < 64 * 64; i += 256) {
            int nd = i >> 6, k = i & 63;
            int n = n0 + nd;
            float pv = (n < N_NODES) ? hprev[(size_t)n * 64 + k] : 0.f;
            hp16[nd * 72 + k] = __float2half(pv);
        }
        __syncthreads();

        float acc[2][4][3][4];
        #pragma unroll
        for (int mt = 0; mt < 2; mt++)
            #pragma unroll
            for (int m = 0; m < 4; m++)
                #pragma unroll
                for (int nt = 0; nt < 3; nt++)
                    #pragma unroll
                    for (int c = 0; c < 4; c++) acc[mt][m][nt][c] = 0.f;

        #pragma unroll
        for (int mt = 0; mt < 2; mt++) {
            const __half* A = mt ? hp16 : h16;
            #pragma unroll
            for (int ks = 0; ks < 4; ks++) {
                #pragma unroll
                for (int m = 0; m < 4; m++) {
                    int row = m * 16 + g;
                    int ko = ks * 16 + 2 * t;
                    uint32_t a0 = *(const uint32_t*)&A[row * 72 + ko];
                    uint32_t a1 = *(const uint32_t*)&A[(row + 8) * 72 + ko];
                    uint32_t a2 = *(const uint32_t*)&A[row * 72 + ko + 8];
                    uint32_t a3 = *(const uint32_t*)&A[(row + 8) * 72 + ko + 8];
                    #pragma unroll
                    for (int nt = 0; nt < 3; nt++) {
                        if (mt == 0) {
                            MMA16816(acc[0][m][nt][0], acc[0][m][nt][1],
                                     acc[0][m][nt][2], acc[0][m][nt][3],
                                     a0, a1, a2, a3, Bi[nt][ks][0], Bi[nt][ks][1]);
                        } else {
                            MMA16816(acc[1][m][nt][0], acc[1][m][nt][1],
                                     acc[1][m][nt][2], acc[1][m][nt][3],
                                     a0, a1, a2, a3, Bh[nt][ks][0], Bh[nt][ks][1]);
                        }
                    }
                }
            }
        }

        #pragma unroll
        for (int mt = 0; mt < 2; mt++) {
            float* st = stage + mt * 12544;
            #pragma unroll
            for (int m = 0; m < 4; m++) {
                int row = m * 16 + g;
                #pragma unroll
                for (int nt = 0; nt < 3; nt++) {
                    int col = cbase + nt * 8 + 2 * t;
                    *(float2*)&st[row * 196 + col] =
                        make_float2(acc[mt][m][nt][0], acc[mt][m][nt][1]);
                    *(float2*)&st[(row + 8) * 196 + col] =
                        make_float2(acc[mt][m][nt][2], acc[mt][m][nt][3]);
                }
            }
        }
        __syncthreads();

        for (int i = tid; i < 64 * 64; i += 256) {
            int nd = i >> 6, j = i & 63;
            int n = n0 + nd;
            float ir = stage[nd * 196 + j]        + bihS[j];
            float iz = stage[nd * 196 + j + 64]   + bihS[64 + j];
            float in_ = stage[nd * 196 + j + 128] + bihS[128 + j];
            float hr = stage[12544 + nd * 196 + j]        + bhhS[j];
            float hz = stage[12544 + nd * 196 + j + 64]   + bhhS[64 + j];
            float hn = stage[12544 + nd * 196 + j + 128]  + bhhS[128 + j];
            float hp = (n < N_NODES) ? hprev[(size_t)n * 64 + j] : 0.f;
            float r = sigf(ir + hr);
            float z = sigf(iz + hz);
            float nn = tanhf(in_ + r * hn);
            float hx = (1.f - z) * nn + z * hp;
            if (n < N_NODES) out_h[(size_t)n * 64 + j] = hx;
            hnS[nd * 68 + j] = hx;
        }
        __syncthreads();

        if (tid < 192) {
            int nd = tid / 3, k = tid % 3;
            int n = n0 + nd;
            if (n < N_NODES) {
                float a = boS[k];
                #pragma unroll
                for (int j = 0; j < 64; j++) a += hnS[nd * 68 + j] * woS[j * 3 + k];
                out_p[(size_t)n * 3 + k] = a;
            }
        }
        __syncthreads();
    }
}

extern "C" void kernel_launch(void* const* d_in, const int* in_sizes, int n_in,
                              void* d_out, int out_size) {
    const float* x       = (const float*)d_in[0];
    const float* h_prev  = (const float*)d_in[1];
    const int* en        = (const int*)d_in[2];
    const int* eh        = (const int*)d_in[3];
    const int* ea        = (const int*)d_in[4];
    const float* W_conv  = (const float*)d_in[5];
    const float* b_conv  = (const float*)d_in[6];
    const float* W_mix   = (const float*)d_in[7];
    const float* b_mix   = (const float*)d_in[8];
    const float* W_ih    = (const float*)d_in[9];
    const float* W_hh    = (const float*)d_in[10];
    const float* b_ih    = (const float*)d_in[11];
    const float* b_hh    = (const float*)d_in[12];
    const float* W_out   = (const float*)d_in[13];
    const float* b_out   = (const float*)d_in[14];
    float* out = (float*)d_out;
    float* out_h = out;
    float* out_p = out + (size_t)N_NODES * 64;

    static const int mixmma_smem = 64 * 136 * 2 + 256;
    static const int gru_smem = 34628 * 4;
    cudaFuncSetAttribute(k_mix_mma, cudaFuncAttributeMaxDynamicSharedMemorySize, mixmma_smem);
    cudaFuncSetAttribute(k_gru_mma, cudaFuncAttributeMaxDynamicSharedMemorySize, gru_smem);

    k_xw_hist<<<XW_PERS + HIST_BLOCKS, 256>>>(x, W_conv, en, eh, ea);     // 0
    k_scan<<<NBB + NBD, 256>>>();                                          // 1
    k_place<<<(NE + 255) / 256, 256>>>(en, eh, ea);                        // 2
    k_gather1<<<(SB * 8 + 255) / 256, 256>>>();                            // 3 <- ncu
    k_gather2<<<(SD * 8 + 255) / 256, 256>>>(b_conv);                      // 4
    k_mix_mma<<<152, 256, mixmma_smem>>>(W_mix, b_mix);                    // 5
    k_gru_mma<<<152, 256, gru_smem>>>(h_prev, W_ih, W_hh, b_ih, b_hh,      // 6
                                      W_out, b_out, out_h, out_p);
}

// round 15
// speedup vs baseline: 1.0819x; 1.0819x over previous
#include <cuda_runtime.h>
#include <cuda_fp16.h>
#include <cstdint>

#define N_NODES 100000
#define M_HE    200000
#define NE      2000000
#define IN_F    16
#define HID     64
#define NT      2

#define SB (NT * M_HE)     // 400000
#define SD (NT * N_NODES)  // 200000
#define NBB ((SB + 1023) / 1024)   // 391
#define NBD ((SD + 1023) / 1024)   // 196
#define TILES ((N_NODES + 63) / 64)  // 1563
#define XW_BLOCKS (N_NODES / 16)     // 6250
#define HIST_BLOCKS ((NE + 255) / 256)
#define GB1 12500                   // gather1 blocks (SB*8/256)
#define PDB ((NE + 255) / 256)      // placeD blocks = 7813
#define FUSE_GROUPS 1563            // groups of 13: 5 placeD + 8 gather1

// ---------------- scratch ----------------
__device__ __align__(16) __half g_xw_h[(size_t)N_NODES * 128];
__device__ __align__(16) __half g_efeat_h[(size_t)M_HE * 128];
__device__ __align__(16) __half g_u_h[(size_t)N_NODES * 128];
__device__ __align__(16) __half g_h_h[(size_t)N_NODES * HID];
__device__ int g_hB[SB], g_hD[SD];
__device__ int g_offB[SB + 1], g_offD[SD + 1];
__device__ int g_curB[SB], g_curD[SD];
__device__ unsigned long long g_flagB[NBB], g_flagD[NBD];
__device__ int g_idxB[NE];
__device__ int g_idxD[NE];

// ---------------- launch 0: xw projection + histogram + flag zero (R10) ----------------
__global__ void k_xw_hist(const float* __restrict__ x, const float* __restrict__ Wc,
                          const int* __restrict__ en, const int* __restrict__ eh,
                          const int* __restrict__ ea) {
    if (blockIdx.x < XW_BLOCKS) {
        __shared__ float Ws[NT * IN_F * HID];
        __shared__ float xs[16 * IN_F];
        int tid = threadIdx.x;
        int n0 = blockIdx.x * 16;
        for (int i = tid; i < NT * IN_F * HID; i += 256) Ws[i] = Wc[i];
        xs[tid] = x[(size_t)n0 * IN_F + tid];
        __syncthreads();
        int c = tid & 127;
        int hf = tid >> 7;
        int t = c >> 6, cc = c & 63;
        const float* w = &Ws[t * (IN_F * HID) + cc];
        #pragma unroll
        for (int nd = 0; nd < 8; nd++) {
            int node = n0 + hf * 8 + nd;
            float a = 0.f;
            #pragma unroll
            for (int k = 0; k < IN_F; k++) a += xs[(hf * 8 + nd) * IN_F + k] * w[k * HID];
            float a_hi = __shfl_down_sync(0xffffffffu, a, 1);
            if ((c & 1) == 0) {
                __half2 hv = __floats2half2_rn(a, a_hi);
                ((__half2*)g_xw_h)[((size_t)node * 128 + c) >> 1] = hv;
            }
        }
    } else {
        int hb = blockIdx.x - XW_BLOCKS;
        if (hb == 0) {
            for (int f = threadIdx.x; f < NBB; f += 256) g_flagB[f] = 0ull;
            for (int f = threadIdx.x; f < NBD; f += 256) g_flagD[f] = 0ull;
        }
        int i = hb * 256 + threadIdx.x;
        if (i >= NE) return;
        int t = ea[i];
        atomicAdd(&g_hB[t * M_HE + eh[i]], 1);
        atomicAdd(&g_hD[t * N_NODES + en[i]], 1);
    }
}

// ---------------- launch 1: single-pass scan (decoupled lookback) ----------------
__global__ void k_scan() {
    int b = blockIdx.x;
    bool isD = (b >= NBB);
    int cb = isD ? b - NBB : b;
    const int n = isD ? SD : SB;
    const int nb = isD ? NBD : NBB;
    int* hist = isD ? g_hD : g_hB;
    int* out  = isD ? g_offD : g_offB;
    int* cur  = isD ? g_curD : g_curB;
    volatile unsigned long long* flags = isD ? g_flagD : g_flagB;

    int tid = threadIdx.x;
    int base = cb * 1024 + tid * 4;
    int v0 = (base + 0 < n) ? hist[base + 0] : 0;
    int v1 = (base + 1 < n) ? hist[base + 1] : 0;
    int v2 = (base + 2 < n) ? hist[base + 2] : 0;
    int v3 = (base + 3 < n) ? hist[base + 3] : 0;
    if (base + 0 < n) hist[base + 0] = 0;
    if (base + 1 < n) hist[base + 1] = 0;
    if (base + 2 < n) hist[base + 2] = 0;
    if (base + 3 < n) hist[base + 3] = 0;
    int s = v0 + v1 + v2 + v3;
    __shared__ int sh[256];
    __shared__ int s_prev;
    sh[tid] = s;
    __syncthreads();
    for (int d = 1; d < 256; d <<= 1) {
        int v = (tid >= d) ? sh[tid - d] : 0;
        __syncthreads();
        sh[tid] += v;
        __syncthreads();
    }
    int excl = sh[tid] - s;

    if (tid == 255) {
        int total = excl + s;
        int prev = 0;
        if (cb == 0) {
            flags[0] = (2ull << 62) | (unsigned long long)(unsigned)total;
        } else {
            flags[cb] = (1ull << 62) | (unsigned long long)(unsigned)total;
            for (int p = cb - 1; p >= 0; p--) {
                unsigned long long f;
                do { f = flags[p]; } while ((f >> 62) == 0ull);
                prev += (int)(unsigned)(f & 0xffffffffull);
                if ((f >> 62) == 2ull) break;
            }
            flags[cb] = (2ull << 62) | (unsigned long long)(unsigned)(prev + total);
        }
        s_prev = prev;
    }
    __syncthreads();
    int p0 = s_prev + excl;
    if (base + 0 < n) { out[base + 0] = p0;                cur[base + 0] = p0; }
    if (base + 1 < n) { out[base + 1] = p0 + v0;           cur[base + 1] = p0 + v0; }
    if (base + 2 < n) { out[base + 2] = p0 + v0 + v1;      cur[base + 2] = p0 + v0 + v1; }
    if (base + 3 < n) { out[base + 3] = p0 + v0 + v1 + v2; cur[base + 3] = p0 + v0 + v1 + v2; }
    if (tid == 0 && cb == nb - 1) out[n] = NE;
}

// ---------------- launch 2: placement, B side only ----------------
__global__ void k_placeB(const int* __restrict__ en, const int* __restrict__ eh,
                         const int* __restrict__ ea) {
    int i = blockIdx.x * blockDim.x + threadIdx.x;
    if (i >= NE) return;
    int t = ea[i], n = en[i], he = eh[i];
    int pb = atomicAdd(&g_curB[t * M_HE + he], 1);
    g_idxB[pb] = n;
}

__device__ __forceinline__ void accum8(float* s, uint4 v) {
    const __half2* h = (const __half2*)&v;
    #pragma unroll
    for (int i = 0; i < 4; i++) {
        float2 f = __half22float2(h[i]);
        s[2 * i]     += f.x;
        s[2 * i + 1] += f.y;
    }
}

__device__ __forceinline__ void accum4x(float* s, uint4 v0, uint4 v1, uint4 v2, uint4 v3) {
    const __half2* h0 = (const __half2*)&v0;
    const __half2* h1 = (const __half2*)&v1;
    const __half2* h2 = (const __half2*)&v2;
    const __half2* h3 = (const __half2*)&v3;
    #pragma unroll
    for (int i = 0; i < 4; i++) {
        __half2 ss = __hadd2(__hadd2(h0[i], h1[i]), __hadd2(h2[i], h3[i]));
        float2 f = __half22float2(ss);
        s[2 * i]     += f.x;
        s[2 * i + 1] += f.y;
    }
}

// ---------------- launch 3 (ncu): gather1 interleaved with placeD ----------------
// groups of 13 blocks: pos 0-4 -> placeD chunk, pos 5-12 -> gather1 chunk.
__global__ void k_gather1_placeD(const int* __restrict__ en, const int* __restrict__ eh,
                                 const int* __restrict__ ea) {
    int grp = blockIdx.x / 13, pos = blockIdx.x % 13;
    int tid = threadIdx.x;

    if (pos < 5) {
        // -------- placeD: scatter node-sorted hyperedge ids --------
        int pb = grp * 5 + pos;
        int i = pb * 256 + tid;
        if (i >= NE) return;
        int t = ea[i], n = en[i], he = eh[i];
        int pd = atomicAdd(&g_curD[t * N_NODES + n], 1);
        g_idxD[pd] = he;
        return;
    }

    // -------- gather1 --------
    int gb = grp * 8 + (pos - 5);
    if (gb >= GB1) return;
    int idx = gb * 256 + tid;
    int r = idx >> 3, q = idx & 7;
    if (r >= SB) return;
    int t = (r >= M_HE) ? 1 : 0;
    int he = r - t * M_HE;
    int start = g_offB[r];
    int cnt = g_offB[r + 1] - start;
    const char* xwb = (const char*)g_xw_h + (unsigned)(t * 8 + q) * 16u;
    const int* ip = g_idxB + start;
    float s[8] = {0.f, 0.f, 0.f, 0.f, 0.f, 0.f, 0.f, 0.f};
    int j = 0;
    for (; j + 4 <= cnt; j += 4) {
        unsigned o0 = (unsigned)__ldg(ip + j)     * 256u;
        unsigned o1 = (unsigned)__ldg(ip + j + 1) * 256u;
        unsigned o2 = (unsigned)__ldg(ip + j + 2) * 256u;
        unsigned o3 = (unsigned)__ldg(ip + j + 3) * 256u;
        uint4 v0 = *(const uint4*)(xwb + o0);
        uint4 v1 = *(const uint4*)(xwb + o1);
        uint4 v2 = *(const uint4*)(xwb + o2);
        uint4 v3 = *(const uint4*)(xwb + o3);
        accum4x(s, v0, v1, v2, v3);
    }
    for (; j < cnt; j++) {
        unsigned o = (unsigned)__ldg(ip + j) * 256u;
        accum8(s, *(const uint4*)(xwb + o));
    }
    float binv = (cnt > 0) ? (1.f / (float)cnt) : 0.f;
    uint4 outv;
    __half2* oh = (__half2*)&outv;
    #pragma unroll
    for (int i = 0; i < 4; i++)
        oh[i] = __floats2half2_rn(s[2 * i] * binv, s[2 * i + 1] * binv);
    ((uint4*)g_efeat_h)[(size_t)he * 16 + t * 8 + q] = outv;
}

// ---------------- launch 4: gather 2 (fuses *dinv + b_conv, fp16 out) ----------------
__global__ void k_gather2(const float* __restrict__ bconv) {
    int idx = blockIdx.x * blockDim.x + threadIdx.x;
    int r = idx >> 3, q = idx & 7;
    if (r >= SD) return;
    int t = (r >= N_NODES) ? 1 : 0;
    int n = r - t * N_NODES;
    int start = g_offD[r];
    int cnt = g_offD[r + 1] - start;
    const char* efb = (const char*)g_efeat_h + (unsigned)(t * 8 + q) * 16u;
    const int* ip = g_idxD + start;
    float s[8] = {0.f, 0.f, 0.f, 0.f, 0.f, 0.f, 0.f, 0.f};
    int j = 0;
    for (; j + 4 <= cnt; j += 4) {
        unsigned o0 = (unsigned)__ldg(ip + j)     * 256u;
        unsigned o1 = (unsigned)__ldg(ip + j + 1) * 256u;
        unsigned o2 = (unsigned)__ldg(ip + j + 2) * 256u;
        unsigned o3 = (unsigned)__ldg(ip + j + 3) * 256u;
        uint4 v0 = *(const uint4*)(efb + o0);
        uint4 v1 = *(const uint4*)(efb + o1);
        uint4 v2 = *(const uint4*)(efb + o2);
        uint4 v3 = *(const uint4*)(efb + o3);
        accum4x(s, v0, v1, v2, v3);
    }
    for (; j < cnt; j++) {
        unsigned o = (unsigned)__ldg(ip + j) * 256u;
        accum8(s, *(const uint4*)(efb + o));
    }
    float dinv = (cnt > 0) ? (1.f / (float)cnt) : 0.f;
    int cbase = t * 64 + q * 8;
    float4 b0 = *(const float4*)(bconv + cbase);
    float4 b1 = *(const float4*)(bconv + cbase + 4);
    uint4 outv;
    __half2* oh = (__half2*)&outv;
    oh[0] = __floats2half2_rn(s[0] * dinv + b0.x, s[1] * dinv + b0.y);
    oh[1] = __floats2half2_rn(s[2] * dinv + b0.z, s[3] * dinv + b0.w);
    oh[2] = __floats2half2_rn(s[4] * dinv + b1.x, s[5] * dinv + b1.y);
    oh[3] = __floats2half2_rn(s[6] * dinv + b1.z, s[7] * dinv + b1.w);
    ((uint4*)g_u_h)[(size_t)n * 16 + t * 8 + q] = outv;
}

__device__ __forceinline__ float sigf(float x) { return 1.f / (1.f + expf(-x)); }

#define MMA16816(c0, c1, c2, c3, a0, a1, a2, a3, b0, b1) \
    asm volatile("mma.sync.aligned.m16n8k16.row.col.f32.f16.f16.f32 " \
                 "{%0,%1,%2,%3}, {%4,%5,%6,%7}, {%8,%9}, {%0,%1,%2,%3};" \
                 : "+f"(c0), "+f"(c1), "+f"(c2), "+f"(c3) \
                 : "r"(a0), "r"(a1), "r"(a2), "r"(a3), "r"(b0), "r"(b1))

// ---------------- launch 5: mix via MMA (persistent) ----------------
__global__ __launch_bounds__(256, 1)
void k_mix_mma(const float* __restrict__ Wmix, const float* __restrict__ bmix) {
    extern __shared__ __half sbuf[];
    __half* buf = sbuf;
    int tid = threadIdx.x;
    int lane = tid & 31;
    int wrp = tid >> 5;
    int g = lane >> 2;
    int t = lane & 3;

    for (int i = tid; i < 64 * 128; i += 256) {
        int n = i >> 7, k = i & 127;
        buf[n * 136 + k] = __float2half(Wmix[k * 64 + n]);
    }
    __syncthreads();

    uint32_t Bm[8][2];
    {
        int n = wrp * 8 + g;
        #pragma unroll
        for (int ks = 0; ks < 8; ks++) {
            Bm[ks][0] = *(const uint32_t*)&buf[n * 136 + ks * 16 + 2 * t];
            Bm[ks][1] = *(const uint32_t*)&buf[n * 136 + ks * 16 + 2 * t + 8];
        }
    }
    int col = wrp * 8 + 2 * t;
    float bm0 = bmix[col], bm1 = bmix[col + 1];
    __syncthreads();

    for (int tile = blockIdx.x; tile < TILES; tile += gridDim.x) {
        int n0 = tile * 64;
        for (int i = tid; i < 1024; i += 256) {
            int nd = i >> 4, c8 = (i & 15) * 8;
            int n = n0 + nd;
            uint4 v = make_uint4(0u, 0u, 0u, 0u);
            if (n < N_NODES) v = ((const uint4*)g_u_h)[(size_t)n * 16 + (c8 >> 3)];
            *(uint4*)&buf[nd * 136 + c8] = v;
        }
        __syncthreads();

        float am[4][4];
        #pragma unroll
        for (int m = 0; m < 4; m++)
            #pragma unroll
            for (int c = 0; c < 4; c++) am[m][c] = 0.f;

        #pragma unroll
        for (int ks = 0; ks < 8; ks++) {
            #pragma unroll
            for (int m = 0; m < 4; m++) {
                int row = m * 16 + g;
                int ko = ks * 16 + 2 * t;
                uint32_t a0 = *(const uint32_t*)&buf[row * 136 + ko];
                uint32_t a1 = *(const uint32_t*)&buf[(row + 8) * 136 + ko];
                uint32_t a2 = *(const uint32_t*)&buf[row * 136 + ko + 8];
                uint32_t a3 = *(const uint32_t*)&buf[(row + 8) * 136 + ko + 8];
                MMA16816(am[m][0], am[m][1], am[m][2], am[m][3],
                         a0, a1, a2, a3, Bm[ks][0], Bm[ks][1]);
            }
        }

        #pragma unroll
        for (int m = 0; m < 4; m++) {
            int row = m * 16 + g;
            int na = n0 + row, nb = n0 + row + 8;
            if (na < N_NODES) {
                __half2 hv = __floats2half2_rn(fmaxf(am[m][0] + bm0, 0.f),
                                               fmaxf(am[m][1] + bm1, 0.f));
                *(__half2*)&g_h_h[(size_t)na * 64 + col] = hv;
            }
            if (nb < N_NODES) {
                __half2 hv = __floats2half2_rn(fmaxf(am[m][2] + bm0, 0.f),
                                               fmaxf(am[m][3] + bm1, 0.f));
                *(__half2*)&g_h_h[(size_t)nb * 64 + col] = hv;
            }
        }
        __syncthreads();
    }
}

// ---------------- launch 6: GRU via fp16 mma.sync (persistent) ----------------
__global__ __launch_bounds__(256, 1)
void k_gru_mma(const float* __restrict__ hprev,
               const float* __restrict__ Wih, const float* __restrict__ Whh,
               const float* __restrict__ bih, const float* __restrict__ bhh,
               const float* __restrict__ Wout, const float* __restrict__ bout,
               float* __restrict__ out_h, float* __restrict__ out_p) {
    extern __shared__ float smf[];
    float*  stage = smf;                          // [2][64][196]
    __half* Wih16 = (__half*)smf;                 // [192][72]
    __half* Whh16 = Wih16 + 192 * 72;             // [192][72]
    __half* h16   = (__half*)(smf + 25088);       // [64][72]
    __half* hp16  = h16 + 64 * 72;                // [64][72]
    float*  hnS   = smf + 29696;                  // [64][68]
    float*  bihS  = smf + 34048;
    float*  bhhS  = bihS + 192;
    float*  woS   = bhhS + 192;
    float*  boS   = woS + 192;

    int tid = threadIdx.x;
    int lane = tid & 31;
    int wrp = tid >> 5;
    int g = lane >> 2;
    int t = lane & 3;
    int cbase = wrp * 24;

    if (tid < 192) {
        bihS[tid] = bih[tid];
        bhhS[tid] = bhh[tid];
        int j = tid / 3, k = tid % 3;
        woS[tid] = Wout[j * 64 + k];
    }
    if (tid < 3) boS[tid] = bout[tid];

    for (int i = tid; i < 192 * 64; i += 256) {
        int r = i >> 6, k = i & 63;
        Wih16[r * 72 + k] = __float2half(Wih[i]);
        Whh16[r * 72 + k] = __float2half(Whh[i]);
    }
    __syncthreads();

    uint32_t Bi[3][4][2], Bh[3][4][2];
    #pragma unroll
    for (int nt = 0; nt < 3; nt++) {
        int n = cbase + nt * 8 + g;
        #pragma unroll
        for (int ks = 0; ks < 4; ks++) {
            Bi[nt][ks][0] = *(const uint32_t*)&Wih16[n * 72 + ks * 16 + 2 * t];
            Bi[nt][ks][1] = *(const uint32_t*)&Wih16[n * 72 + ks * 16 + 2 * t + 8];
            Bh[nt][ks][0] = *(const uint32_t*)&Whh16[n * 72 + ks * 16 + 2 * t];
            Bh[nt][ks][1] = *(const uint32_t*)&Whh16[n * 72 + ks * 16 + 2 * t + 8];
        }
    }
    __syncthreads();

    for (int tile = blockIdx.x; tile < TILES; tile += gridDim.x) {
        int n0 = tile * 64;
        for (int i = tid; i < 512; i += 256) {
            int nd = i >> 3, c8 = (i & 7) * 8;
            int n = n0 + nd;
            uint4 v = make_uint4(0u, 0u, 0u, 0u);
            if (n < N_NODES) v = ((const uint4*)g_h_h)[(size_t)n * 8 + (c8 >> 3)];
            *(uint4*)&h16[nd * 72 + c8] = v;
        }
        for (int i = tid; i < 64 * 64; i += 256) {
            int nd = i >> 6, k = i & 63;
            int n = n0 + nd;
            float pv = (n < N_NODES) ? hprev[(size_t)n * 64 + k] : 0.f;
            hp16[nd * 72 + k] = __float2half(pv);
        }
        __syncthreads();

        float acc[2][4][3][4];
        #pragma unroll
        for (int mt = 0; mt < 2; mt++)
            #pragma unroll
            for (int m = 0; m < 4; m++)
                #pragma unroll
                for (int nt = 0; nt < 3; nt++)
                    #pragma unroll
                    for (int c = 0; c < 4; c++) acc[mt][m][nt][c] = 0.f;

        #pragma unroll
        for (int mt = 0; mt < 2; mt++) {
            const __half* A = mt ? hp16 : h16;
            #pragma unroll
            for (int ks = 0; ks < 4; ks++) {
                #pragma unroll
                for (int m = 0; m < 4; m++) {
                    int row = m * 16 + g;
                    int ko = ks * 16 + 2 * t;
                    uint32_t a0 = *(const uint32_t*)&A[row * 72 + ko];
                    uint32_t a1 = *(const uint32_t*)&A[(row + 8) * 72 + ko];
                    uint32_t a2 = *(const uint32_t*)&A[row * 72 + ko + 8];
                    uint32_t a3 = *(const uint32_t*)&A[(row + 8) * 72 + ko + 8];
                    #pragma unroll
                    for (int nt = 0; nt < 3; nt++) {
                        if (mt == 0) {
                            MMA16816(acc[0][m][nt][0], acc[0][m][nt][1],
                                     acc[0][m][nt][2], acc[0][m][nt][3],
                                     a0, a1, a2, a3, Bi[nt][ks][0], Bi[nt][ks][1]);
                        } else {
                            MMA16816(acc[1][m][nt][0], acc[1][m][nt][1],
                                     acc[1][m][nt][2], acc[1][m][nt][3],
                                     a0, a1, a2, a3, Bh[nt][ks][0], Bh[nt][ks][1]);
                        }
                    }
                }
            }
        }

        #pragma unroll
        for (int mt = 0; mt < 2; mt++) {
            float* st = stage + mt * 12544;
            #pragma unroll
            for (int m = 0; m < 4; m++) {
                int row = m * 16 + g;
                #pragma unroll
                for (int nt = 0; nt < 3; nt++) {
                    int col = cbase + nt * 8 + 2 * t;
                    *(float2*)&st[row * 196 + col] =
                        make_float2(acc[mt][m][nt][0], acc[mt][m][nt][1]);
                    *(float2*)&st[(row + 8) * 196 + col] =
                        make_float2(acc[mt][m][nt][2], acc[mt][m][nt][3]);
                }
            }
        }
        __syncthreads();

        for (int i = tid; i < 64 * 64; i += 256) {
            int nd = i >> 6, j = i & 63;
            int n = n0 + nd;
            float ir = stage[nd * 196 + j]        + bihS[j];
            float iz = stage[nd * 196 + j + 64]   + bihS[64 + j];
            float in_ = stage[nd * 196 + j + 128] + bihS[128 + j];
            float hr = stage[12544 + nd * 196 + j]        + bhhS[j];
            float hz = stage[12544 + nd * 196 + j + 64]   + bhhS[64 + j];
            float hn = stage[12544 + nd * 196 + j + 128]  + bhhS[128 + j];
            float hp = (n < N_NODES) ? hprev[(size_t)n * 64 + j] : 0.f;
            float r = sigf(ir + hr);
            float z = sigf(iz + hz);
            float nn = tanhf(in_ + r * hn);
            float hx = (1.f - z) * nn + z * hp;
            if (n < N_NODES) out_h[(size_t)n * 64 + j] = hx;
            hnS[nd * 68 + j] = hx;
        }
        __syncthreads();

        if (tid < 192) {
            int nd = tid / 3, k = tid % 3;
            int n = n0 + nd;
            if (n < N_NODES) {
                float a = boS[k];
                #pragma unroll
                for (int j = 0; j < 64; j++) a += hnS[nd * 68 + j] * woS[j * 3 + k];
                out_p[(size_t)n * 3 + k] = a;
            }
        }
        __syncthreads();
    }
}

extern "C" void kernel_launch(void* const* d_in, const int* in_sizes, int n_in,
                              void* d_out, int out_size) {
    const float* x       = (const float*)d_in[0];
    const float* h_prev  = (const float*)d_in[1];
    const int* en        = (const int*)d_in[2];
    const int* eh        = (const int*)d_in[3];
    const int* ea        = (const int*)d_in[4];
    const float* W_conv  = (const float*)d_in[5];
    const float* b_conv  = (const float*)d_in[6];
    const float* W_mix   = (const float*)d_in[7];
    const float* b_mix   = (const float*)d_in[8];
    const float* W_ih    = (const float*)d_in[9];
    const float* W_hh    = (const float*)d_in[10];
    const float* b_ih    = (const float*)d_in[11];
    const float* b_hh    = (const float*)d_in[12];
    const float* W_out   = (const float*)d_in[13];
    const float* b_out   = (const float*)d_in[14];
    float* out = (float*)d_out;
    float* out_h = out;
    float* out_p = out + (size_t)N_NODES * 64;

    static const int mixmma_smem = 64 * 136 * 2 + 256;
    static const int gru_smem = 34628 * 4;
    cudaFuncSetAttribute(k_mix_mma, cudaFuncAttributeMaxDynamicSharedMemorySize, mixmma_smem);
    cudaFuncSetAttribute(k_gru_mma, cudaFuncAttributeMaxDynamicSharedMemorySize, gru_smem);

    k_xw_hist<<<XW_BLOCKS + HIST_BLOCKS, 256>>>(x, W_conv, en, eh, ea);   // 0
    k_scan<<<NBB + NBD, 256>>>();                                          // 1
    k_placeB<<<(NE + 255) / 256, 256>>>(en, eh, ea);                       // 2
    k_gather1_placeD<<<FUSE_GROUPS * 13, 256>>>(en, eh, ea);               // 3 <- ncu
    k_gather2<<<(SD * 8 + 255) / 256, 256>>>(b_conv);                      // 4
    k_mix_mma<<<152, 256, mixmma_smem>>>(W_mix, b_mix);                    // 5
    k_gru_mma<<<152, 256, gru_smem>>>(h_prev, W_ih, W_hh, b_ih, b_hh,      // 6
                                      W_out, b_out, out_h, out_p);
}

// round 16
// speedup vs baseline: 1.0911x; 1.0085x over previous
#include <cuda_runtime.h>
#include <cuda_fp16.h>
#include <cstdint>

#define N_NODES 100000
#define M_HE    200000
#define NE      2000000
#define IN_F    16
#define HID     64
#define NT      2

#define SB (NT * M_HE)     // 400000
#define SD (NT * N_NODES)  // 200000
#define NBB ((SB + 1023) / 1024)   // 391
#define NBD ((SD + 1023) / 1024)   // 196
#define TILES ((N_NODES + 63) / 64)  // 1563
#define XW_BLOCKS (N_NODES / 16)     // 6250
#define HIST_BLOCKS ((NE + 255) / 256)  // 7813
#define L0_GROUPS 1563              // groups of 9: 4 xw + 5 hist
#define GB1 12500                   // gather1 blocks (SB*8/256)
#define FUSE_GROUPS 1563            // groups of 13: 5 placeD + 8 gather1

// ---------------- scratch ----------------
__device__ __align__(16) __half g_xw_h[(size_t)N_NODES * 128];
__device__ __align__(16) __half g_efeat_h[(size_t)M_HE * 128];
__device__ __align__(16) __half g_u_h[(size_t)N_NODES * 128];
__device__ __align__(16) __half g_h_h[(size_t)N_NODES * HID];
__device__ int g_hB[SB], g_hD[SD];
__device__ int g_offB[SB + 1], g_offD[SD + 1];
__device__ int g_curB[SB], g_curD[SD];
__device__ unsigned long long g_flagB[NBB], g_flagD[NBD];
__device__ int g_idxB[NE];
__device__ int g_idxD[NE];

// ---------------- launch 0: interleaved xw projection ∥ histogram + flag zero ----------------
// groups of 9 blocks: pos 0-3 -> xw tile, pos 4-8 -> hist chunk.
__global__ void k_xw_hist(const float* __restrict__ x, const float* __restrict__ Wc,
                          const int* __restrict__ en, const int* __restrict__ eh,
                          const int* __restrict__ ea) {
    int grp = blockIdx.x / 9, pos = blockIdx.x % 9;
    int tid = threadIdx.x;

    if (pos < 4) {
        // -------- xw: project 16 nodes --------
        int xb = grp * 4 + pos;
        if (xb >= XW_BLOCKS) return;
        __shared__ float Ws[NT * IN_F * HID];
        __shared__ float xs[16 * IN_F];
        int n0 = xb * 16;
        for (int i = tid; i < NT * IN_F * HID; i += 256) Ws[i] = Wc[i];
        xs[tid] = x[(size_t)n0 * IN_F + tid];
        __syncthreads();
        int c = tid & 127;
        int hf = tid >> 7;
        int t = c >> 6, cc = c & 63;
        const float* w = &Ws[t * (IN_F * HID) + cc];
        #pragma unroll
        for (int nd = 0; nd < 8; nd++) {
            int node = n0 + hf * 8 + nd;
            float a = 0.f;
            #pragma unroll
            for (int k = 0; k < IN_F; k++) a += xs[(hf * 8 + nd) * IN_F + k] * w[k * HID];
            float a_hi = __shfl_down_sync(0xffffffffu, a, 1);
            if ((c & 1) == 0) {
                __half2 hv = __floats2half2_rn(a, a_hi);
                ((__half2*)g_xw_h)[((size_t)node * 128 + c) >> 1] = hv;
            }
        }
    } else {
        // -------- hist --------
        int hb = grp * 5 + (pos - 4);
        if (hb == 0) {
            for (int f = tid; f < NBB; f += 256) g_flagB[f] = 0ull;
            for (int f = tid; f < NBD; f += 256) g_flagD[f] = 0ull;
        }
        if (hb >= HIST_BLOCKS) return;
        int i = hb * 256 + tid;
        if (i >= NE) return;
        int t = ea[i];
        atomicAdd(&g_hB[t * M_HE + eh[i]], 1);
        atomicAdd(&g_hD[t * N_NODES + en[i]], 1);
    }
}

// ---------------- launch 1: single-pass scan (decoupled lookback) ----------------
__global__ void k_scan() {
    int b = blockIdx.x;
    bool isD = (b >= NBB);
    int cb = isD ? b - NBB : b;
    const int n = isD ? SD : SB;
    const int nb = isD ? NBD : NBB;
    int* hist = isD ? g_hD : g_hB;
    int* out  = isD ? g_offD : g_offB;
    int* cur  = isD ? g_curD : g_curB;
    volatile unsigned long long* flags = isD ? g_flagD : g_flagB;

    int tid = threadIdx.x;
    int base = cb * 1024 + tid * 4;
    int v0 = (base + 0 < n) ? hist[base + 0] : 0;
    int v1 = (base + 1 < n) ? hist[base + 1] : 0;
    int v2 = (base + 2 < n) ? hist[base + 2] : 0;
    int v3 = (base + 3 < n) ? hist[base + 3] : 0;
    if (base + 0 < n) hist[base + 0] = 0;
    if (base + 1 < n) hist[base + 1] = 0;
    if (base + 2 < n) hist[base + 2] = 0;
    if (base + 3 < n) hist[base + 3] = 0;
    int s = v0 + v1 + v2 + v3;
    __shared__ int sh[256];
    __shared__ int s_prev;
    sh[tid] = s;
    __syncthreads();
    for (int d = 1; d < 256; d <<= 1) {
        int v = (tid >= d) ? sh[tid - d] : 0;
        __syncthreads();
        sh[tid] += v;
        __syncthreads();
    }
    int excl = sh[tid] - s;

    if (tid == 255) {
        int total = excl + s;
        int prev = 0;
        if (cb == 0) {
            flags[0] = (2ull << 62) | (unsigned long long)(unsigned)total;
        } else {
            flags[cb] = (1ull << 62) | (unsigned long long)(unsigned)total;
            for (int p = cb - 1; p >= 0; p--) {
                unsigned long long f;
                do { f = flags[p]; } while ((f >> 62) == 0ull);
                prev += (int)(unsigned)(f & 0xffffffffull);
                if ((f >> 62) == 2ull) break;
            }
            flags[cb] = (2ull << 62) | (unsigned long long)(unsigned)(prev + total);
        }
        s_prev = prev;
    }
    __syncthreads();
    int p0 = s_prev + excl;
    if (base + 0 < n) { out[base + 0] = p0;                cur[base + 0] = p0; }
    if (base + 1 < n) { out[base + 1] = p0 + v0;           cur[base + 1] = p0 + v0; }
    if (base + 2 < n) { out[base + 2] = p0 + v0 + v1;      cur[base + 2] = p0 + v0 + v1; }
    if (base + 3 < n) { out[base + 3] = p0 + v0 + v1 + v2; cur[base + 3] = p0 + v0 + v1 + v2; }
    if (tid == 0 && cb == nb - 1) out[n] = NE;
}

// ---------------- launch 2: placement, B side only ----------------
__global__ void k_placeB(const int* __restrict__ en, const int* __restrict__ eh,
                         const int* __restrict__ ea) {
    int i = blockIdx.x * blockDim.x + threadIdx.x;
    if (i >= NE) return;
    int t = ea[i], n = en[i], he = eh[i];
    int pb = atomicAdd(&g_curB[t * M_HE + he], 1);
    g_idxB[pb] = n;
}

__device__ __forceinline__ void accum8(float* s, uint4 v) {
    const __half2* h = (const __half2*)&v;
    #pragma unroll
    for (int i = 0; i < 4; i++) {
        float2 f = __half22float2(h[i]);
        s[2 * i]     += f.x;
        s[2 * i + 1] += f.y;
    }
}

__device__ __forceinline__ void accum4x(float* s, uint4 v0, uint4 v1, uint4 v2, uint4 v3) {
    const __half2* h0 = (const __half2*)&v0;
    const __half2* h1 = (const __half2*)&v1;
    const __half2* h2 = (const __half2*)&v2;
    const __half2* h3 = (const __half2*)&v3;
    #pragma unroll
    for (int i = 0; i < 4; i++) {
        __half2 ss = __hadd2(__hadd2(h0[i], h1[i]), __hadd2(h2[i], h3[i]));
        float2 f = __half22float2(ss);
        s[2 * i]     += f.x;
        s[2 * i + 1] += f.y;
    }
}

// ---------------- launch 3 (ncu): gather1 interleaved with placeD ----------------
__global__ void k_gather1_placeD(const int* __restrict__ en, const int* __restrict__ eh,
                                 const int* __restrict__ ea) {
    int grp = blockIdx.x / 13, pos = blockIdx.x % 13;
    int tid = threadIdx.x;

    if (pos < 5) {
        int pb = grp * 5 + pos;
        int i = pb * 256 + tid;
        if (i >= NE) return;
        int t = ea[i], n = en[i], he = eh[i];
        int pd = atomicAdd(&g_curD[t * N_NODES + n], 1);
        g_idxD[pd] = he;
        return;
    }

    int gb = grp * 8 + (pos - 5);
    if (gb >= GB1) return;
    int idx = gb * 256 + tid;
    int r = idx >> 3, q = idx & 7;
    if (r >= SB) return;
    int t = (r >= M_HE) ? 1 : 0;
    int he = r - t * M_HE;
    int start = g_offB[r];
    int cnt = g_offB[r + 1] - start;
    const char* xwb = (const char*)g_xw_h + (unsigned)(t * 8 + q) * 16u;
    const int* ip = g_idxB + start;
    float s[8] = {0.f, 0.f, 0.f, 0.f, 0.f, 0.f, 0.f, 0.f};
    int j = 0;
    for (; j + 4 <= cnt; j += 4) {
        unsigned o0 = (unsigned)__ldg(ip + j)     * 256u;
        unsigned o1 = (unsigned)__ldg(ip + j + 1) * 256u;
        unsigned o2 = (unsigned)__ldg(ip + j + 2) * 256u;
        unsigned o3 = (unsigned)__ldg(ip + j + 3) * 256u;
        uint4 v0 = *(const uint4*)(xwb + o0);
        uint4 v1 = *(const uint4*)(xwb + o1);
        uint4 v2 = *(const uint4*)(xwb + o2);
        uint4 v3 = *(const uint4*)(xwb + o3);
        accum4x(s, v0, v1, v2, v3);
    }
    for (; j < cnt; j++) {
        unsigned o = (unsigned)__ldg(ip + j) * 256u;
        accum8(s, *(const uint4*)(xwb + o));
    }
    float binv = (cnt > 0) ? (1.f / (float)cnt) : 0.f;
    uint4 outv;
    __half2* oh = (__half2*)&outv;
    #pragma unroll
    for (int i = 0; i < 4; i++)
        oh[i] = __floats2half2_rn(s[2 * i] * binv, s[2 * i + 1] * binv);
    ((uint4*)g_efeat_h)[(size_t)he * 16 + t * 8 + q] = outv;
}

// ---------------- launch 4: gather 2 (fuses *dinv + b_conv, fp16 out) ----------------
__global__ void k_gather2(const float* __restrict__ bconv) {
    int idx = blockIdx.x * blockDim.x + threadIdx.x;
    int r = idx >> 3, q = idx & 7;
    if (r >= SD) return;
    int t = (r >= N_NODES) ? 1 : 0;
    int n = r - t * N_NODES;
    int start = g_offD[r];
    int cnt = g_offD[r + 1] - start;
    const char* efb = (const char*)g_efeat_h + (unsigned)(t * 8 + q) * 16u;
    const int* ip = g_idxD + start;
    float s[8] = {0.f, 0.f, 0.f, 0.f, 0.f, 0.f, 0.f, 0.f};
    int j = 0;
    for (; j + 4 <= cnt; j += 4) {
        unsigned o0 = (unsigned)__ldg(ip + j)     * 256u;
        unsigned o1 = (unsigned)__ldg(ip + j + 1) * 256u;
        unsigned o2 = (unsigned)__ldg(ip + j + 2) * 256u;
        unsigned o3 = (unsigned)__ldg(ip + j + 3) * 256u;
        uint4 v0 = *(const uint4*)(efb + o0);
        uint4 v1 = *(const uint4*)(efb + o1);
        uint4 v2 = *(const uint4*)(efb + o2);
        uint4 v3 = *(const uint4*)(efb + o3);
        accum4x(s, v0, v1, v2, v3);
    }
    for (; j < cnt; j++) {
        unsigned o = (unsigned)__ldg(ip + j) * 256u;
        accum8(s, *(const uint4*)(efb + o));
    }
    float dinv = (cnt > 0) ? (1.f / (float)cnt) : 0.f;
    int cbase = t * 64 + q * 8;
    float4 b0 = *(const float4*)(bconv + cbase);
    float4 b1 = *(const float4*)(bconv + cbase + 4);
    uint4 outv;
    __half2* oh = (__half2*)&outv;
    oh[0] = __floats2half2_rn(s[0] * dinv + b0.x, s[1] * dinv + b0.y);
    oh[1] = __floats2half2_rn(s[2] * dinv + b0.z, s[3] * dinv + b0.w);
    oh[2] = __floats2half2_rn(s[4] * dinv + b1.x, s[5] * dinv + b1.y);
    oh[3] = __floats2half2_rn(s[6] * dinv + b1.z, s[7] * dinv + b1.w);
    ((uint4*)g_u_h)[(size_t)n * 16 + t * 8 + q] = outv;
}

__device__ __forceinline__ float sigf(float x) { return 1.f / (1.f + expf(-x)); }

#define MMA16816(c0, c1, c2, c3, a0, a1, a2, a3, b0, b1) \
    asm volatile("mma.sync.aligned.m16n8k16.row.col.f32.f16.f16.f32 " \
                 "{%0,%1,%2,%3}, {%4,%5,%6,%7}, {%8,%9}, {%0,%1,%2,%3};" \
                 : "+f"(c0), "+f"(c1), "+f"(c2), "+f"(c3) \
                 : "r"(a0), "r"(a1), "r"(a2), "r"(a3), "r"(b0), "r"(b1))

// ---------------- launch 5: mix via MMA (persistent) ----------------
__global__ __launch_bounds__(256, 1)
void k_mix_mma(const float* __restrict__ Wmix, const float* __restrict__ bmix) {
    extern __shared__ __half sbuf[];
    __half* buf = sbuf;
    int tid = threadIdx.x;
    int lane = tid & 31;
    int wrp = tid >> 5;
    int g = lane >> 2;
    int t = lane & 3;

    for (int i = tid; i < 64 * 128; i += 256) {
        int n = i >> 7, k = i & 127;
        buf[n * 136 + k] = __float2half(Wmix[k * 64 + n]);
    }
    __syncthreads();

    uint32_t Bm[8][2];
    {
        int n = wrp * 8 + g;
        #pragma unroll
        for (int ks = 0; ks < 8; ks++) {
            Bm[ks][0] = *(const uint32_t*)&buf[n * 136 + ks * 16 + 2 * t];
            Bm[ks][1] = *(const uint32_t*)&buf[n * 136 + ks * 16 + 2 * t + 8];
        }
    }
    int col = wrp * 8 + 2 * t;
    float bm0 = bmix[col], bm1 = bmix[col + 1];
    __syncthreads();

    for (int tile = blockIdx.x; tile < TILES; tile += gridDim.x) {
        int n0 = tile * 64;
        for (int i = tid; i < 1024; i += 256) {
            int nd = i >> 4, c8 = (i & 15) * 8;
            int n = n0 + nd;
            uint4 v = make_uint4(0u, 0u, 0u, 0u);
            if (n < N_NODES) v = ((const uint4*)g_u_h)[(size_t)n * 16 + (c8 >> 3)];
            *(uint4*)&buf[nd * 136 + c8] = v;
        }
        __syncthreads();

        float am[4][4];
        #pragma unroll
        for (int m = 0; m < 4; m++)
            #pragma unroll
            for (int c = 0; c < 4; c++) am[m][c] = 0.f;

        #pragma unroll
        for (int ks = 0; ks < 8; ks++) {
            #pragma unroll
            for (int m = 0; m < 4; m++) {
                int row = m * 16 + g;
                int ko = ks * 16 + 2 * t;
                uint32_t a0 = *(const uint32_t*)&buf[row * 136 + ko];
                uint32_t a1 = *(const uint32_t*)&buf[(row + 8) * 136 + ko];
                uint32_t a2 = *(const uint32_t*)&buf[row * 136 + ko + 8];
                uint32_t a3 = *(const uint32_t*)&buf[(row + 8) * 136 + ko + 8];
                MMA16816(am[m][0], am[m][1], am[m][2], am[m][3],
                         a0, a1, a2, a3, Bm[ks][0], Bm[ks][1]);
            }
        }

        #pragma unroll
        for (int m = 0; m < 4; m++) {
            int row = m * 16 + g;
            int na = n0 + row, nb = n0 + row + 8;
            if (na < N_NODES) {
                __half2 hv = __floats2half2_rn(fmaxf(am[m][0] + bm0, 0.f),
                                               fmaxf(am[m][1] + bm1, 0.f));
                *(__half2*)&g_h_h[(size_t)na * 64 + col] = hv;
            }
            if (nb < N_NODES) {
                __half2 hv = __floats2half2_rn(fmaxf(am[m][2] + bm0, 0.f),
                                               fmaxf(am[m][3] + bm1, 0.f));
                *(__half2*)&g_h_h[(size_t)nb * 64 + col] = hv;
            }
        }
        __syncthreads();
    }
}

// ---------------- launch 6: GRU via fp16 mma.sync (persistent) ----------------
__global__ __launch_bounds__(256, 1)
void k_gru_mma(const float* __restrict__ hprev,
               const float* __restrict__ Wih, const float* __restrict__ Whh,
               const float* __restrict__ bih, const float* __restrict__ bhh,
               const float* __restrict__ Wout, const float* __restrict__ bout,
               float* __restrict__ out_h, float* __restrict__ out_p) {
    extern __shared__ float smf[];
    float*  stage = smf;                          // [2][64][196]
    __half* Wih16 = (__half*)smf;                 // [192][72]
    __half* Whh16 = Wih16 + 192 * 72;             // [192][72]
    __half* h16   = (__half*)(smf + 25088);       // [64][72]
    __half* hp16  = h16 + 64 * 72;                // [64][72]
    float*  hnS   = smf + 29696;                  // [64][68]
    float*  bihS  = smf + 34048;
    float*  bhhS  = bihS + 192;
    float*  woS   = bhhS + 192;
    float*  boS   = woS + 192;

    int tid = threadIdx.x;
    int lane = tid & 31;
    int wrp = tid >> 5;
    int g = lane >> 2;
    int t = lane & 3;
    int cbase = wrp * 24;

    if (tid < 192) {
        bihS[tid] = bih[tid];
        bhhS[tid] = bhh[tid];
        int j = tid / 3, k = tid % 3;
        woS[tid] = Wout[j * 64 + k];
    }
    if (tid < 3) boS[tid] = bout[tid];

    for (int i = tid; i < 192 * 64; i += 256) {
        int r = i >> 6, k = i & 63;
        Wih16[r * 72 + k] = __float2half(Wih[i]);
        Whh16[r * 72 + k] = __float2half(Whh[i]);
    }
    __syncthreads();

    uint32_t Bi[3][4][2], Bh[3][4][2];
    #pragma unroll
    for (int nt = 0; nt < 3; nt++) {
        int n = cbase + nt * 8 + g;
        #pragma unroll
        for (int ks = 0; ks < 4; ks++) {
            Bi[nt][ks][0] = *(const uint32_t*)&Wih16[n * 72 + ks * 16 + 2 * t];
            Bi[nt][ks][1] = *(const uint32_t*)&Wih16[n * 72 + ks * 16 + 2 * t + 8];
            Bh[nt][ks][0] = *(const uint32_t*)&Whh16[n * 72 + ks * 16 + 2 * t];
            Bh[nt][ks][1] = *(const uint32_t*)&Whh16[n * 72 + ks * 16 + 2 * t + 8];
        }
    }
    __syncthreads();

    for (int tile = blockIdx.x; tile < TILES; tile += gridDim.x) {
        int n0 = tile * 64;
        for (int i = tid; i < 512; i += 256) {
            int nd = i >> 3, c8 = (i & 7) * 8;
            int n = n0 + nd;
            uint4 v = make_uint4(0u, 0u, 0u, 0u);
            if (n < N_NODES) v = ((const uint4*)g_h_h)[(size_t)n * 8 + (c8 >> 3)];
            *(uint4*)&h16[nd * 72 + c8] = v;
        }
        for (int i = tid; i < 64 * 64; i += 256) {
            int nd = i >> 6, k = i & 63;
            int n = n0 + nd;
            float pv = (n < N_NODES) ? hprev[(size_t)n * 64 + k] : 0.f;
            hp16[nd * 72 + k] = __float2half(pv);
        }
        __syncthreads();

        float acc[2][4][3][4];
        #pragma unroll
        for (int mt = 0; mt < 2; mt++)
            #pragma unroll
            for (int m = 0; m < 4; m++)
                #pragma unroll
                for (int nt = 0; nt < 3; nt++)
                    #pragma unroll
                    for (int c = 0; c < 4; c++) acc[mt][m][nt][c] = 0.f;

        #pragma unroll
        for (int mt = 0; mt < 2; mt++) {
            const __half* A = mt ? hp16 : h16;
            #pragma unroll
            for (int ks = 0; ks < 4; ks++) {
                #pragma unroll
                for (int m = 0; m < 4; m++) {
                    int row = m * 16 + g;
                    int ko = ks * 16 + 2 * t;
                    uint32_t a0 = *(const uint32_t*)&A[row * 72 + ko];
                    uint32_t a1 = *(const uint32_t*)&A[(row + 8) * 72 + ko];
                    uint32_t a2 = *(const uint32_t*)&A[row * 72 + ko + 8];
                    uint32_t a3 = *(const uint32_t*)&A[(row + 8) * 72 + ko + 8];
                    #pragma unroll
                    for (int nt = 0; nt < 3; nt++) {
                        if (mt == 0) {
                            MMA16816(acc[0][m][nt][0], acc[0][m][nt][1],
                                     acc[0][m][nt][2], acc[0][m][nt][3],
                                     a0, a1, a2, a3, Bi[nt][ks][0], Bi[nt][ks][1]);
                        } else {
                            MMA16816(acc[1][m][nt][0], acc[1][m][nt][1],
                                     acc[1][m][nt][2], acc[1][m][nt][3],
                                     a0, a1, a2, a3, Bh[nt][ks][0], Bh[nt][ks][1]);
                        }
                    }
                }
            }
        }

        #pragma unroll
        for (int mt = 0; mt < 2; mt++) {
            float* st = stage + mt * 12544;
            #pragma unroll
            for (int m = 0; m < 4; m++) {
                int row = m * 16 + g;
                #pragma unroll
                for (int nt = 0; nt < 3; nt++) {
                    int col = cbase + nt * 8 + 2 * t;
                    *(float2*)&st[row * 196 + col] =
                        make_float2(acc[mt][m][nt][0], acc[mt][m][nt][1]);
                    *(float2*)&st[(row + 8) * 196 + col] =
                        make_float2(acc[mt][m][nt][2], acc[mt][m][nt][3]);
                }
            }
        }
        __syncthreads();

        for (int i = tid; i < 64 * 64; i += 256) {
            int nd = i >> 6, j = i & 63;
            int n = n0 + nd;
            float ir = stage[nd * 196 + j]        + bihS[j];
            float iz = stage[nd * 196 + j + 64]   + bihS[64 + j];
            float in_ = stage[nd * 196 + j + 128] + bihS[128 + j];
            float hr = stage[12544 + nd * 196 + j]        + bhhS[j];
            float hz = stage[12544 + nd * 196 + j + 64]   + bhhS[64 + j];
            float hn = stage[12544 + nd * 196 + j + 128]  + bhhS[128 + j];
            float hp = (n < N_NODES) ? hprev[(size_t)n * 64 + j] : 0.f;
            float r = sigf(ir + hr);
            float z = sigf(iz + hz);
            float nn = tanhf(in_ + r * hn);
            float hx = (1.f - z) * nn + z * hp;
            if (n < N_NODES) out_h[(size_t)n * 64 + j] = hx;
            hnS[nd * 68 + j] = hx;
        }
        __syncthreads();

        if (tid < 192) {
            int nd = tid / 3, k = tid % 3;
            int n = n0 + nd;
            if (n < N_NODES) {
                float a = boS[k];
                #pragma unroll
                for (int j = 0; j < 64; j++) a += hnS[nd * 68 + j] * woS[j * 3 + k];
                out_p[(size_t)n * 3 + k] = a;
            }
        }
        __syncthreads();
    }
}

extern "C" void kernel_launch(void* const* d_in, const int* in_sizes, int n_in,
                              void* d_out, int out_size) {
    const float* x       = (const float*)d_in[0];
    const float* h_prev  = (const float*)d_in[1];
    const int* en        = (const int*)d_in[2];
    const int* eh        = (const int*)d_in[3];
    const int* ea        = (const int*)d_in[4];
    const float* W_conv  = (const float*)d_in[5];
    const float* b_conv  = (const float*)d_in[6];
    const float* W_mix   = (const float*)d_in[7];
    const float* b_mix   = (const float*)d_in[8];
    const float* W_ih    = (const float*)d_in[9];
    const float* W_hh    = (const float*)d_in[10];
    const float* b_ih    = (const float*)d_in[11];
    const float* b_hh    = (const float*)d_in[12];
    const float* W_out   = (const float*)d_in[13];
    const float* b_out   = (const float*)d_in[14];
    float* out = (float*)d_out;
    float* out_h = out;
    float* out_p = out + (size_t)N_NODES * 64;

    static const int mixmma_smem = 64 * 136 * 2 + 256;
    static const int gru_smem = 34628 * 4;
    cudaFuncSetAttribute(k_mix_mma, cudaFuncAttributeMaxDynamicSharedMemorySize, mixmma_smem);
    cudaFuncSetAttribute(k_gru_mma, cudaFuncAttributeMaxDynamicSharedMemorySize, gru_smem);

    k_xw_hist<<<L0_GROUPS * 9, 256>>>(x, W_conv, en, eh, ea);             // 0
    k_scan<<<NBB + NBD, 256>>>();                                          // 1
    k_placeB<<<(NE + 255) / 256, 256>>>(en, eh, ea);                       // 2
    k_gather1_placeD<<<FUSE_GROUPS * 13, 256>>>(en, eh, ea);               // 3 <- ncu
    k_gather2<<<(SD * 8 + 255) / 256, 256>>>(b_conv);                      // 4
    k_mix_mma<<<152, 256, mixmma_smem>>>(W_mix, b_mix);                    // 5
    k_gru_mma<<<152, 256, gru_smem>>>(h_prev, W_ih, W_hh, b_ih, b_hh,      // 6
                                      W_out, b_out, out_h, out_p);
}